// round 12
// baseline (speedup 1.0000x reference)
#include <cuda_runtime.h>
#include <cuda_bf16.h>
#include <cstdint>

// Unfold3d: x (B=4, C=32, D=16, H=48, W=48) fp32, K=3, PAD=1, STR=1, DIL=1.
// out[b][c*27 + kidx][d*HW + h*W + w] = x[b][c][d+kd-1][h+kh-1][w+kw-1] (0 OOB)
//
// R9: best-known structure (R5, 82.1us): one CTA per (d, bc), packed
// halo-free smem planes 3x48x48 = 27.6KB -> 8 CTAs/SM, predicated row/col
// edges, fully unrolled 27-channel store loop. Single remaining untested
// lever: __stwt write-through stores (vs __stcs / write-back, both ~82us) --
// skips L2 write-allocate + dirty-eviction for the 510MB write-once stream.
// Writes alone already run at ~6.2 TB/s = approx the HBM write ceiling.

#define B_  4
#define C_  32
#define D_  16
#define H_  48
#define W_  48
#define HW  (H_ * W_)          // 2304
#define DHW (D_ * HW)          // 36864
#define W4  (W_ / 4)           // 12
#define SPLANE HW              // packed plane, 2304 floats
#define SMEM_FLOATS (3 * SPLANE)  // 6912 floats = 27648 B

__global__ __launch_bounds__(192, 8) void unfold3d_kernel(
    const float* __restrict__ x, float* __restrict__ out)
{
    __shared__ float s[SMEM_FLOATS];

    const int d  = blockIdx.x;          // 0..15
    const int bc = blockIdx.y;          // 0..127

    const int w4 = threadIdx.x;         // 0..11
    const int hb = threadIdx.y;         // 0..15

    // ---- Phase 1: copy 3 planes (d-1, d, d+1) into packed smem ----
    {
        const float* __restrict__ xb = x + (size_t)bc * DHW;
        #pragma unroll
        for (int p = 0; p < 3; p++) {
            const int dd = d + p - 1;
            float* __restrict__ sp = s + p * SPLANE;
            if ((unsigned)dd < (unsigned)D_) {
                const float* __restrict__ plane = xb + dd * HW;
                #pragma unroll
                for (int k = 0; k < 3; k++) {
                    const int r = hb + k * 16;
                    *reinterpret_cast<float4*>(sp + r * W_ + w4 * 4) =
                        *reinterpret_cast<const float4*>(plane + r * W_ + w4 * 4);
                }
            } else {
                #pragma unroll
                for (int k = 0; k < 3; k++) {
                    const int r = hb + k * 16;
                    *reinterpret_cast<float4*>(sp + r * W_ + w4 * 4) =
                        make_float4(0.f, 0.f, 0.f, 0.f);
                }
            }
        }
    }
    __syncthreads();

    // ---- Phase 2: 27 channel tiles, predicated edges, write-through ----
    float* __restrict__ ob = out + (size_t)bc * 27 * DHW + (size_t)d * HW;

    #pragma unroll
    for (int k = 0; k < 3; k++) {
        const int h = hb + k * 16;                    // 0..47
        float* __restrict__ obase = ob + h * W_ + w4 * 4;

        #pragma unroll
        for (int kh = 0; kh < 3; kh++) {
            const int hh = h + kh - 1;                // -1..48
            const bool rok = (unsigned)hh < (unsigned)H_;

            #pragma unroll
            for (int kd = 0; kd < 3; kd++) {
                const float* __restrict__ p =
                    s + kd * SPLANE + hh * W_ + w4 * 4;

                float4 q = make_float4(0.f, 0.f, 0.f, 0.f);
                float pw = 0.f, nx = 0.f;
                if (rok) {
                    q = *reinterpret_cast<const float4*>(p);
                    if (w4 > 0)       pw = p[-1];     // input col 4w4-1
                    if (w4 < W4 - 1)  nx = p[4];      // input col 4w4+4
                }

                float* o = obase + ((kd * 3 + kh) * 3) * DHW;
                __stwt(reinterpret_cast<float4*>(o),
                       make_float4(pw, q.x, q.y, q.z));            // kw=0
                __stwt(reinterpret_cast<float4*>(o + DHW), q);     // kw=1
                __stwt(reinterpret_cast<float4*>(o + 2 * DHW),
                       make_float4(q.y, q.z, q.w, nx));            // kw=2
            }
        }
    }
}

extern "C" void kernel_launch(void* const* d_in, const int* in_sizes, int n_in,
                              void* d_out, int out_size)
{
    const float* x = (const float*)d_in[0];
    float* out = (float*)d_out;

    dim3 grid(D_, B_ * C_);        // 16 x 128 = 2048 blocks
    dim3 block(W4, 16);            // 192 threads
    unfold3d_kernel<<<grid, block>>>(x, out);
}

// round 16
// speedup vs baseline: 1.0827x; 1.0827x over previous
#include <cuda_runtime.h>
#include <cuda_bf16.h>
#include <cstdint>

// Unfold3d: x (B=4, C=32, D=16, H=48, W=48) fp32, K=3, PAD=1, STR=1, DIL=1.
// out[b][c*27 + kidx][d*HW + h*W + w] = x[b][c][d+kd-1][h+kh-1][w+kw-1] (0 OOB)
//
// FINAL (== R5, best measured 82.1us): one CTA per (d, bc); three packed
// halo-free input planes staged in 27.6KB smem (8 CTAs/SM); fully unrolled
// 3x3x3 store loop with predicated row/col edges; __stcs evict-first float4
// stores. Roofline-settled: the 510MB compulsory write stream runs at
// ~6.2 TB/s, the HBM write-path ceiling on this part. Nine structural
// variants (loop orders, occupancy 46-68%, store policies stcs/wb/wt,
// persistent + balanced single-wave grids) all land within 82-94us.

#define B_  4
#define C_  32
#define D_  16
#define H_  48
#define W_  48
#define HW  (H_ * W_)          // 2304
#define DHW (D_ * HW)          // 36864
#define W4  (W_ / 4)           // 12
#define SPLANE HW              // packed plane, 2304 floats
#define SMEM_FLOATS (3 * SPLANE)  // 6912 floats = 27648 B

__global__ __launch_bounds__(192, 8) void unfold3d_kernel(
    const float* __restrict__ x, float* __restrict__ out)
{
    __shared__ float s[SMEM_FLOATS];

    const int d  = blockIdx.x;          // 0..15
    const int bc = blockIdx.y;          // 0..127

    const int w4 = threadIdx.x;         // 0..11
    const int hb = threadIdx.y;         // 0..15

    // ---- Phase 1: copy 3 planes (d-1, d, d+1) into packed smem ----
    {
        const float* __restrict__ xb = x + (size_t)bc * DHW;
        #pragma unroll
        for (int p = 0; p < 3; p++) {
            const int dd = d + p - 1;
            float* __restrict__ sp = s + p * SPLANE;
            if ((unsigned)dd < (unsigned)D_) {
                const float* __restrict__ plane = xb + dd * HW;
                #pragma unroll
                for (int k = 0; k < 3; k++) {
                    const int r = hb + k * 16;
                    *reinterpret_cast<float4*>(sp + r * W_ + w4 * 4) =
                        *reinterpret_cast<const float4*>(plane + r * W_ + w4 * 4);
                }
            } else {
                #pragma unroll
                for (int k = 0; k < 3; k++) {
                    const int r = hb + k * 16;
                    *reinterpret_cast<float4*>(sp + r * W_ + w4 * 4) =
                        make_float4(0.f, 0.f, 0.f, 0.f);
                }
            }
        }
    }
    __syncthreads();

    // ---- Phase 2: 27 channel tiles, predicated edges ----
    float* __restrict__ ob = out + (size_t)bc * 27 * DHW + (size_t)d * HW;

    #pragma unroll
    for (int k = 0; k < 3; k++) {
        const int h = hb + k * 16;                    // 0..47
        float* __restrict__ obase = ob + h * W_ + w4 * 4;

        #pragma unroll
        for (int kh = 0; kh < 3; kh++) {
            const int hh = h + kh - 1;                // -1..48
            const bool rok = (unsigned)hh < (unsigned)H_;

            #pragma unroll
            for (int kd = 0; kd < 3; kd++) {
                const float* __restrict__ p =
                    s + kd * SPLANE + hh * W_ + w4 * 4;

                float4 q = make_float4(0.f, 0.f, 0.f, 0.f);
                float pw = 0.f, nx = 0.f;
                if (rok) {
                    q = *reinterpret_cast<const float4*>(p);
                    if (w4 > 0)       pw = p[-1];     // input col 4w4-1
                    if (w4 < W4 - 1)  nx = p[4];      // input col 4w4+4
                }

                float* o = obase + ((kd * 3 + kh) * 3) * DHW;
                __stcs(reinterpret_cast<float4*>(o),
                       make_float4(pw, q.x, q.y, q.z));            // kw=0
                __stcs(reinterpret_cast<float4*>(o + DHW), q);     // kw=1
                __stcs(reinterpret_cast<float4*>(o + 2 * DHW),
                       make_float4(q.y, q.z, q.w, nx));            // kw=2
            }
        }
    }
}

extern "C" void kernel_launch(void* const* d_in, const int* in_sizes, int n_in,
                              void* d_out, int out_size)
{
    const float* x = (const float*)d_in[0];
    float* out = (float*)d_out;

    dim3 grid(D_, B_ * C_);        // 16 x 128 = 2048 blocks
    dim3 block(W4, 16);            // 192 threads
    unfold3d_kernel<<<grid, block>>>(x, out);
}

// round 17
// speedup vs baseline: 1.0856x; 1.0027x over previous
#include <cuda_runtime.h>
#include <cuda_bf16.h>
#include <cstdint>

// Unfold3d: x (B=4, C=32, D=16, H=48, W=48) fp32, K=3, PAD=1, STR=1, DIL=1.
// out[b][c*27 + kidx][d*HW + h*W + w] = x[b][c][d+kd-1][h+kh-1][w+kw-1] (0 OOB)
//
// FINAL (best measured 82.1us, reproduced 82.4us): one CTA per (d, bc);
// three packed halo-free input planes staged in 27.6KB smem (8 CTAs/SM);
// fully unrolled 3x3x3 store loop with predicated row/col edges; __stcs
// evict-first float4 stores (each warp store = one contiguous 512B line).
//
// Roofline-settled: the compulsory 510MB write stream runs at ~6.2 TB/s,
// the HBM write-path ceiling on this part. Ten structural variants (loop
// orders, occupancy 46-68%, packed vs haloed smem, store policies
// stcs/write-back/write-through, persistent grid, balanced single-wave grid)
// all land in 82-94us at 5.4-5.7 TB/s ncu-DRAM with L2/issue/ALU far from
// saturation. No SM-side lever moves the write ceiling; TMA stores share the
// same LTS/DRAM path and the kernel is not issue-bound.

#define B_  4
#define C_  32
#define D_  16
#define H_  48
#define W_  48
#define HW  (H_ * W_)          // 2304
#define DHW (D_ * HW)          // 36864
#define W4  (W_ / 4)           // 12
#define SPLANE HW              // packed plane, 2304 floats
#define SMEM_FLOATS (3 * SPLANE)  // 6912 floats = 27648 B

__global__ __launch_bounds__(192, 8) void unfold3d_kernel(
    const float* __restrict__ x, float* __restrict__ out)
{
    __shared__ float s[SMEM_FLOATS];

    const int d  = blockIdx.x;          // 0..15
    const int bc = blockIdx.y;          // 0..127

    const int w4 = threadIdx.x;         // 0..11
    const int hb = threadIdx.y;         // 0..15

    // ---- Phase 1: copy 3 planes (d-1, d, d+1) into packed smem ----
    {
        const float* __restrict__ xb = x + (size_t)bc * DHW;
        #pragma unroll
        for (int p = 0; p < 3; p++) {
            const int dd = d + p - 1;
            float* __restrict__ sp = s + p * SPLANE;
            if ((unsigned)dd < (unsigned)D_) {
                const float* __restrict__ plane = xb + dd * HW;
                #pragma unroll
                for (int k = 0; k < 3; k++) {
                    const int r = hb + k * 16;
                    *reinterpret_cast<float4*>(sp + r * W_ + w4 * 4) =
                        *reinterpret_cast<const float4*>(plane + r * W_ + w4 * 4);
                }
            } else {
                #pragma unroll
                for (int k = 0; k < 3; k++) {
                    const int r = hb + k * 16;
                    *reinterpret_cast<float4*>(sp + r * W_ + w4 * 4) =
                        make_float4(0.f, 0.f, 0.f, 0.f);
                }
            }
        }
    }
    __syncthreads();

    // ---- Phase 2: 27 channel tiles, predicated edges ----
    float* __restrict__ ob = out + (size_t)bc * 27 * DHW + (size_t)d * HW;

    #pragma unroll
    for (int k = 0; k < 3; k++) {
        const int h = hb + k * 16;                    // 0..47
        float* __restrict__ obase = ob + h * W_ + w4 * 4;

        #pragma unroll
        for (int kh = 0; kh < 3; kh++) {
            const int hh = h + kh - 1;                // -1..48
            const bool rok = (unsigned)hh < (unsigned)H_;

            #pragma unroll
            for (int kd = 0; kd < 3; kd++) {
                const float* __restrict__ p =
                    s + kd * SPLANE + hh * W_ + w4 * 4;

                float4 q = make_float4(0.f, 0.f, 0.f, 0.f);
                float pw = 0.f, nx = 0.f;
                if (rok) {
                    q = *reinterpret_cast<const float4*>(p);
                    if (w4 > 0)       pw = p[-1];     // input col 4w4-1
                    if (w4 < W4 - 1)  nx = p[4];      // input col 4w4+4
                }

                float* o = obase + ((kd * 3 + kh) * 3) * DHW;
                __stcs(reinterpret_cast<float4*>(o),
                       make_float4(pw, q.x, q.y, q.z));            // kw=0
                __stcs(reinterpret_cast<float4*>(o + DHW), q);     // kw=1
                __stcs(reinterpret_cast<float4*>(o + 2 * DHW),
                       make_float4(q.y, q.z, q.w, nx));            // kw=2
            }
        }
    }
}

extern "C" void kernel_launch(void* const* d_in, const int* in_sizes, int n_in,
                              void* d_out, int out_size)
{
    const float* x = (const float*)d_in[0];
    float* out = (float*)d_out;

    dim3 grid(D_, B_ * C_);        // 16 x 128 = 2048 blocks
    dim3 block(W4, 16);            // 192 threads
    unfold3d_kernel<<<grid, block>>>(x, out);
}